// round 5
// baseline (speedup 1.0000x reference)
#include <cuda_runtime.h>
#include <cstdint>

#define B_GR   2048
#define N_NODE 64
#define E_PG   512
#define TOT_N  (B_GR * N_NODE)     // 131072
#define TOT_E  (B_GR * E_PG)       // 1048576
#define D_EMB  64
#define STATE_W 4160               // 64*64 + 64
#define HID    512
#define MASK_N 8388608u            // TOT_N * D_EMB

// ---------------- scratch (static device arrays; no runtime alloc) ---------
__device__ float    g_xm[TOT_N * D_EMB];        // x @ W_msg
__device__ float    g_xs[TOT_N * D_EMB];        // x @ W_self + b_self
__device__ float    g_states[B_GR * STATE_W];   // [node(4096) | user(64)]
__device__ float    g_h1[B_GR * HID];
__device__ float    g_h2[B_GR * (HID / 2)];
__device__ float    g_logits[B_GR * N_NODE];
__device__ unsigned g_mask[MASK_N / 32];

// ------- threefry-2x32 dropout mask, JAX partitionable path, key 42 --------
// element i: counter = (hi, lo) = (0, i); bits = out0 ^ out1;
// keep = (uniform < 0.5) = (bit31(bits) == 0)
__device__ __forceinline__ unsigned rotl32(unsigned v, int s) {
    return (v << s) | (v >> (32 - s));
}

__global__ void __launch_bounds__(256) mask_kernel() {
    unsigned i = blockIdx.x * 256u + threadIdx.x;   // element index
    unsigned x0 = 0u, x1 = i;
    const unsigned k0 = 0u, k1 = 42u, k2 = 0x1BD11BDAu ^ k0 ^ k1;
#define TF4(a, b, c, d)                                  \
    x0 += x1; x1 = rotl32(x1, a); x1 ^= x0;              \
    x0 += x1; x1 = rotl32(x1, b); x1 ^= x0;              \
    x0 += x1; x1 = rotl32(x1, c); x1 ^= x0;              \
    x0 += x1; x1 = rotl32(x1, d); x1 ^= x0;
    x0 += k0; x1 += k1;
    TF4(13, 15, 26, 6)  x0 += k1; x1 += k2 + 1u;
    TF4(17, 29, 16, 24) x0 += k2; x1 += k0 + 2u;
    TF4(13, 15, 26, 6)  x0 += k0; x1 += k1 + 3u;
    TF4(17, 29, 16, 24) x0 += k1; x1 += k2 + 4u;
    TF4(13, 15, 26, 6)  x0 += k2; x1 += k0 + 5u;
#undef TF4
    const unsigned bits = x0 ^ x1;
    unsigned w = __ballot_sync(0xffffffffu, (bits >> 31) == 0u);
    if ((threadIdx.x & 31u) == 0u) g_mask[i >> 5] = w;
}

// ---------------- xm = x @ W_msg ; xs = x @ W_self + b_self ----------------
__global__ void __launch_bounds__(256) xw_kernel(
    const float* __restrict__ x, const float* __restrict__ Wm,
    const float* __restrict__ Ws, const float* __restrict__ bs) {
    __shared__ float sx[64 * 16];
    const int t = threadIdx.x;
    const int row0 = blockIdx.x * 64;
#pragma unroll
    for (int i = 0; i < 4; i++) sx[t + i * 256] = x[row0 * 16 + t + i * 256];

    const int c = t & 63, rl = t >> 6;
    float wm[16], ws[16];
#pragma unroll
    for (int k = 0; k < 16; k++) { wm[k] = Wm[k * 64 + c]; ws[k] = Ws[k * 64 + c]; }
    const float bsc = bs[c];
    __syncthreads();

#pragma unroll 4
    for (int q = 0; q < 16; q++) {
        const int r = rl * 16 + q;
        const float4* xr = (const float4*)&sx[r * 16];
        float4 a0 = xr[0], a1 = xr[1], a2 = xr[2], a3 = xr[3];
        float xk[16] = {a0.x, a0.y, a0.z, a0.w, a1.x, a1.y, a1.z, a1.w,
                        a2.x, a2.y, a2.z, a2.w, a3.x, a3.y, a3.z, a3.w};
        float sm = 0.f, ss = 0.f;
#pragma unroll
        for (int k = 0; k < 16; k++) { sm += xk[k] * wm[k]; ss += xk[k] * ws[k]; }
        const int row = row0 + r;
        g_xm[row * 64 + c] = sm;
        g_xs[row * 64 + c] = ss + bsc;
    }
}

// ------- per-graph: edge scan + dense 64^3 aggregation + relu/dropout ------
// agg[d][c] = xs[d][c] + sum_s C[s->d] * xm[s][c]
//           + EA0[d]*We0[c] + EA1[d]*We1[c] + deg[d]*(b_msg[c]+b_edge[c])
__global__ void __launch_bounds__(256) node_kernel(
    const float* __restrict__ edge_attr, const int* __restrict__ ei,
    const float* __restrict__ W_edge, const float* __restrict__ b_msg,
    const float* __restrict__ b_edge, const float* __restrict__ user_s,
    const float* __restrict__ W1, const float* __restrict__ b1) {
    __shared__ float CT[64 * 64];   // CT[s*64+d] = #edges s->d
    __shared__ float XM[64 * 64];
    __shared__ float sea0[64], sea1[64];
    __shared__ float sWe0[64], sWe1[64], sbc[64];

    const int t = threadIdx.x;
    const int b = blockIdx.x;
    const int base = b * 64;

    // ---- phase 1: zero + stage constants + stage xm tile + user MLP
#pragma unroll
    for (int i = 0; i < 16; i++) CT[t + i * 256] = 0.f;
    if (t < 64) {
        sea0[t] = 0.f; sea1[t] = 0.f;
        sWe0[t] = W_edge[t]; sWe1[t] = W_edge[64 + t];
        sbc[t] = b_msg[t] + b_edge[t];
    }
    {
        const float4* xmg = (const float4*)&g_xm[base * 64];
        float4* xms = (float4*)XM;
#pragma unroll
        for (int i = 0; i < 4; i++) xms[t + i * 256] = xmg[t + i * 256];
    }
    if (t < 64) {   // user = relu(user_s[b] @ W1 + b1)
        float u = b1[t];
#pragma unroll
        for (int k = 0; k < 32; k++) u += user_s[b * 32 + k] * W1[k * 64 + t];
        g_states[b * STATE_W + 4096 + t] = fmaxf(u, 0.f);
    }
    __syncthreads();

    // ---- phase 2: edge scan (3 smem atomics per edge)
#pragma unroll
    for (int i = 0; i < 2; i++) {
        const int e = t + i * 256;
        const int eg = b * E_PG + e;
        const int s = ei[eg] - base;
        const int d = ei[TOT_E + eg] - base;
        const float2 ea = *(const float2*)&edge_attr[2 * eg];
        atomicAdd(&CT[s * 64 + d], 1.0f);
        atomicAdd(&sea0[d], ea.x);
        atomicAdd(&sea1[d], ea.y);
    }
    __syncthreads();

    // ---- phase 3: acc = xs + CT^T @ XM   (4x4 register micro-tile)
    const int tx = t & 15, ty = t >> 4;
    const int ci = tx * 4, dt = ty * 4;
    float acc[4][4];
    float dega[4] = {0.f, 0.f, 0.f, 0.f};
#pragma unroll
    for (int j = 0; j < 4; j++) {
        float4 v = *(const float4*)&g_xs[(base + dt + j) * 64 + ci];
        acc[j][0] = v.x; acc[j][1] = v.y; acc[j][2] = v.z; acc[j][3] = v.w;
    }
#pragma unroll 8
    for (int s = 0; s < 64; s++) {
        const float4 cv = *(const float4*)&CT[s * 64 + dt];
        const float4 xv = *(const float4*)&XM[s * 64 + ci];
        const float cj[4] = {cv.x, cv.y, cv.z, cv.w};
#pragma unroll
        for (int j = 0; j < 4; j++) {
            acc[j][0] += cj[j] * xv.x;
            acc[j][1] += cj[j] * xv.y;
            acc[j][2] += cj[j] * xv.z;
            acc[j][3] += cj[j] * xv.w;
            dega[j]   += cj[j];         // accumulates in-degree of node dt+j
        }
    }

    // ---- phase 4: edge-attr terms + bias*deg + relu + dropout + store
#pragma unroll
    for (int j = 0; j < 4; j++) {
        const int d = dt + j;
        const unsigned mw = g_mask[(unsigned)(base + d) * 2u + (unsigned)(ci >> 5)];
        const float e0 = sea0[d], e1 = sea1[d], dg = dega[j];
        float4 o;
        float* op = (float*)&o;
#pragma unroll
        for (int k = 0; k < 4; k++) {
            const int c = ci + k;
            float val = acc[j][k] + e0 * sWe0[c] + e1 * sWe1[c] + dg * sbc[c];
            val = fmaxf(val, 0.f);
            val = ((mw >> (c & 31)) & 1u) ? val * 2.0f : 0.f;
            op[k] = val;
        }
        *(float4*)&g_states[b * STATE_W + d * 64 + ci] = o;
    }
}

// ---------------- generic tiled GEMM: C = act(A[M,K] @ B[K,N] + bias) ------
// 128x64 tile, 256 threads, 8x4 micro-tile. M=2048, K%16==0, N%64==0.
__global__ void __launch_bounds__(256) gemm_kernel(
    const float* __restrict__ A, const float* __restrict__ Bw,
    const float* __restrict__ bias, float* __restrict__ C,
    int K, int Ntot, int do_relu) {
    __shared__ float As[16][132];
    __shared__ float Bs[16][64];
    const int t = threadIdx.x;
    const int row0 = blockIdx.x * 128;
    const int c0 = blockIdx.y * 64;
    const int tx = t & 15, ty = t >> 4;

    const int ar = t & 127;          // A stage row (both halves)
    const int ak0 = (t >> 7) * 4;    // 0 or 4
    const int ak1 = ak0 + 8;
    const int bkr = t >> 4, bc4 = (t & 15) * 4;

    const float* Arow = A + (size_t)(row0 + ar) * K;
    const float* Bp   = Bw + (size_t)bkr * Ntot + c0 + bc4;

    float4 a0 = *(const float4*)&Arow[ak0];
    float4 a1 = *(const float4*)&Arow[ak1];
    float4 bb = *(const float4*)Bp;

    float acc[8][4];
#pragma unroll
    for (int j = 0; j < 8; j++)
#pragma unroll
        for (int i = 0; i < 4; i++) acc[j][i] = 0.f;

    const int nk = K / 16;
    for (int kt = 0; kt < nk; kt++) {
        __syncthreads();
        As[ak0 + 0][ar] = a0.x; As[ak0 + 1][ar] = a0.y;
        As[ak0 + 2][ar] = a0.z; As[ak0 + 3][ar] = a0.w;
        As[ak1 + 0][ar] = a1.x; As[ak1 + 1][ar] = a1.y;
        As[ak1 + 2][ar] = a1.z; As[ak1 + 3][ar] = a1.w;
        *(float4*)&Bs[bkr][bc4] = bb;
        __syncthreads();
        if (kt + 1 < nk) {
            const int kb = (kt + 1) * 16;
            a0 = *(const float4*)&Arow[kb + ak0];
            a1 = *(const float4*)&Arow[kb + ak1];
            bb = *(const float4*)&Bp[(size_t)16 * Ntot * (kt + 1)];
        }
#pragma unroll
        for (int k = 0; k < 16; k++) {
            const float4 av0 = *(const float4*)&As[k][ty * 8];
            const float4 av1 = *(const float4*)&As[k][ty * 8 + 4];
            const float4 bv  = *(const float4*)&Bs[k][tx * 4];
            const float aa[8] = {av0.x, av0.y, av0.z, av0.w,
                                 av1.x, av1.y, av1.z, av1.w};
            const float bbv[4] = {bv.x, bv.y, bv.z, bv.w};
#pragma unroll
            for (int j = 0; j < 8; j++)
#pragma unroll
                for (int i = 0; i < 4; i++) acc[j][i] += aa[j] * bbv[i];
        }
    }

    const float4 bz = *(const float4*)&bias[c0 + tx * 4];
    const float bzz[4] = {bz.x, bz.y, bz.z, bz.w};
#pragma unroll
    for (int j = 0; j < 8; j++) {
        const int row = row0 + ty * 8 + j;
        float4 o;
        float* op = (float*)&o;
#pragma unroll
        for (int i = 0; i < 4; i++) {
            float v = acc[j][i] + bzz[i];
            op[i] = do_relu ? fmaxf(v, 0.f) : v;
        }
        *(float4*)&C[(size_t)row * Ntot + c0 + tx * 4] = o;
    }
}

// ---------------- softmax across the batch axis (column-wise) --------------
__global__ void __launch_bounds__(256) softmax_kernel(float* __restrict__ out) {
    const int c = blockIdx.x;        // column 0..63
    const int t = threadIdx.x;
    const int lane = t & 31, wid = t >> 5;
    __shared__ float redm[8];
    __shared__ float reds[8];

    float v[8];
    float mx = -1e30f;
#pragma unroll
    for (int i = 0; i < 8; i++) {
        v[i] = g_logits[(i * 256 + t) * 64 + c];
        mx = fmaxf(mx, v[i]);
    }
#pragma unroll
    for (int o = 16; o; o >>= 1) mx = fmaxf(mx, __shfl_xor_sync(~0u, mx, o));
    if (lane == 0) redm[wid] = mx;
    __syncthreads();
    mx = redm[0];
#pragma unroll
    for (int w = 1; w < 8; w++) mx = fmaxf(mx, redm[w]);

    float sum = 0.f;
#pragma unroll
    for (int i = 0; i < 8; i++) { v[i] = expf(v[i] - mx); sum += v[i]; }
#pragma unroll
    for (int o = 16; o; o >>= 1) sum += __shfl_xor_sync(~0u, sum, o);
    if (lane == 0) reds[wid] = sum;
    __syncthreads();
    sum = 0.f;
#pragma unroll
    for (int w = 0; w < 8; w++) sum += reds[w];
    const float inv = 1.0f / sum;

#pragma unroll
    for (int i = 0; i < 8; i++) out[(i * 256 + t) * 64 + c] = v[i] * inv;
}

// ---------------------------------------------------------------------------
extern "C" void kernel_launch(void* const* d_in, const int* in_sizes, int n_in,
                              void* d_out, int out_size) {
    const float* x         = (const float*)d_in[0];
    const float* edge_attr = (const float*)d_in[1];
    const float* user_s    = (const float*)d_in[2];
    const float* W_msg     = (const float*)d_in[3];
    const float* b_msg     = (const float*)d_in[4];
    const float* W_edge    = (const float*)d_in[5];
    const float* b_edge    = (const float*)d_in[6];
    const float* W_self    = (const float*)d_in[7];
    const float* b_self    = (const float*)d_in[8];
    const float* W1        = (const float*)d_in[9];
    const float* b1        = (const float*)d_in[10];
    const float* W2        = (const float*)d_in[11];
    const float* b2        = (const float*)d_in[12];
    const float* W3        = (const float*)d_in[13];
    const float* b3        = (const float*)d_in[14];
    const float* W4        = (const float*)d_in[15];
    const float* b4        = (const float*)d_in[16];
    const int*   ei        = (const int*)d_in[17];
    float* out = (float*)d_out;

    float *states, *h1, *h2, *logits;
    cudaGetSymbolAddress((void**)&states, g_states);
    cudaGetSymbolAddress((void**)&h1, g_h1);
    cudaGetSymbolAddress((void**)&h2, g_h2);
    cudaGetSymbolAddress((void**)&logits, g_logits);

    mask_kernel<<<MASK_N / 256, 256>>>();
    xw_kernel<<<TOT_N / 64, 256>>>(x, W_msg, W_self, b_self);
    node_kernel<<<B_GR, 256>>>(edge_attr, ei, W_edge, b_msg, b_edge,
                               user_s, W1, b1);
    gemm_kernel<<<dim3(B_GR / 128, HID / 64), 256>>>(
        states, W2, b2, h1, STATE_W, HID, 1);
    gemm_kernel<<<dim3(B_GR / 128, (HID / 2) / 64), 256>>>(
        h1, W3, b3, h2, HID, HID / 2, 1);
    gemm_kernel<<<dim3(B_GR / 128, N_NODE / 64), 256>>>(
        h2, W4, b4, logits, HID / 2, N_NODE, 0);
    softmax_kernel<<<N_NODE, 256>>>(out);
}

// round 11
// speedup vs baseline: 1.5721x; 1.5721x over previous
#include <cuda_runtime.h>
#include <cuda_bf16.h>
#include <cstdint>

#define B_GR   2048
#define N_NODE 64
#define E_PG   512
#define TOT_N  (B_GR * N_NODE)     // 131072
#define TOT_E  (B_GR * E_PG)       // 1048576
#define D_EMB  64
#define STATE_W 4160               // 64*64 + 64
#define HID    512
#define MASK_N 8388608u            // TOT_N * D_EMB

// ---------------- scratch (static device arrays; no runtime alloc) ---------
__device__ float    g_xm[TOT_N * D_EMB];        // x @ W_msg
__device__ float    g_xs[TOT_N * D_EMB];        // x @ W_self + b_self
__device__ float    g_states[B_GR * STATE_W];   // [node(4096) | user(64)]
__device__ float    g_h1[B_GR * HID];
__device__ float    g_h2[B_GR * (HID / 2)];
__device__ float    g_logits[B_GR * N_NODE];
__device__ unsigned g_mask[MASK_N / 32];

// ------- threefry-2x32 dropout mask, JAX partitionable path, key 42 --------
__device__ __forceinline__ unsigned rotl32(unsigned v, int s) {
    return (v << s) | (v >> (32 - s));
}

__global__ void __launch_bounds__(256) mask_kernel() {
    unsigned i = blockIdx.x * 256u + threadIdx.x;   // element index
    unsigned x0 = 0u, x1 = i;
    const unsigned k0 = 0u, k1 = 42u, k2 = 0x1BD11BDAu ^ k0 ^ k1;
#define TF4(a, b, c, d)                                  \
    x0 += x1; x1 = rotl32(x1, a); x1 ^= x0;              \
    x0 += x1; x1 = rotl32(x1, b); x1 ^= x0;              \
    x0 += x1; x1 = rotl32(x1, c); x1 ^= x0;              \
    x0 += x1; x1 = rotl32(x1, d); x1 ^= x0;
    x0 += k0; x1 += k1;
    TF4(13, 15, 26, 6)  x0 += k1; x1 += k2 + 1u;
    TF4(17, 29, 16, 24) x0 += k2; x1 += k0 + 2u;
    TF4(13, 15, 26, 6)  x0 += k0; x1 += k1 + 3u;
    TF4(17, 29, 16, 24) x0 += k1; x1 += k2 + 4u;
    TF4(13, 15, 26, 6)  x0 += k2; x1 += k0 + 5u;
#undef TF4
    const unsigned bits = x0 ^ x1;
    unsigned w = __ballot_sync(0xffffffffu, (bits >> 31) == 0u);
    if ((threadIdx.x & 31u) == 0u) g_mask[i >> 5] = w;
}

// ---------------- xm = x @ W_msg ; xs = x @ W_self + b_self ----------------
__global__ void __launch_bounds__(256) xw_kernel(
    const float* __restrict__ x, const float* __restrict__ Wm,
    const float* __restrict__ Ws, const float* __restrict__ bs) {
    __shared__ float sx[64 * 16];
    const int t = threadIdx.x;
    const int row0 = blockIdx.x * 64;
#pragma unroll
    for (int i = 0; i < 4; i++) sx[t + i * 256] = x[row0 * 16 + t + i * 256];

    const int c = t & 63, rl = t >> 6;
    float wm[16], ws[16];
#pragma unroll
    for (int k = 0; k < 16; k++) { wm[k] = Wm[k * 64 + c]; ws[k] = Ws[k * 64 + c]; }
    const float bsc = bs[c];
    __syncthreads();

#pragma unroll 4
    for (int q = 0; q < 16; q++) {
        const int r = rl * 16 + q;
        const float4* xr = (const float4*)&sx[r * 16];
        float4 a0 = xr[0], a1 = xr[1], a2 = xr[2], a3 = xr[3];
        float xk[16] = {a0.x, a0.y, a0.z, a0.w, a1.x, a1.y, a1.z, a1.w,
                        a2.x, a2.y, a2.z, a2.w, a3.x, a3.y, a3.z, a3.w};
        float sm = 0.f, ss = 0.f;
#pragma unroll
        for (int k = 0; k < 16; k++) { sm += xk[k] * wm[k]; ss += xk[k] * ws[k]; }
        const int row = row0 + r;
        g_xm[row * 64 + c] = sm;
        g_xs[row * 64 + c] = ss + bsc;
    }
}

// ------- per-graph: edge scan + dense 64^3 aggregation + relu/dropout ------
__global__ void __launch_bounds__(256) node_kernel(
    const float* __restrict__ edge_attr, const int* __restrict__ ei,
    const float* __restrict__ W_edge, const float* __restrict__ b_msg,
    const float* __restrict__ b_edge, const float* __restrict__ user_s,
    const float* __restrict__ W1, const float* __restrict__ b1) {
    __shared__ float CT[64 * 64];   // CT[s*64+d] = #edges s->d
    __shared__ float XM[64 * 64];
    __shared__ float sea0[64], sea1[64];
    __shared__ float sWe0[64], sWe1[64], sbc[64];

    const int t = threadIdx.x;
    const int b = blockIdx.x;
    const int base = b * 64;

#pragma unroll
    for (int i = 0; i < 16; i++) CT[t + i * 256] = 0.f;
    if (t < 64) {
        sea0[t] = 0.f; sea1[t] = 0.f;
        sWe0[t] = W_edge[t]; sWe1[t] = W_edge[64 + t];
        sbc[t] = b_msg[t] + b_edge[t];
    }
    {
        const float4* xmg = (const float4*)&g_xm[base * 64];
        float4* xms = (float4*)XM;
#pragma unroll
        for (int i = 0; i < 4; i++) xms[t + i * 256] = xmg[t + i * 256];
    }
    if (t < 64) {   // user = relu(user_s[b] @ W1 + b1)
        float u = b1[t];
#pragma unroll
        for (int k = 0; k < 32; k++) u += user_s[b * 32 + k] * W1[k * 64 + t];
        g_states[b * STATE_W + 4096 + t] = fmaxf(u, 0.f);
    }
    __syncthreads();

#pragma unroll
    for (int i = 0; i < 2; i++) {
        const int e = t + i * 256;
        const int eg = b * E_PG + e;
        const int s = ei[eg] - base;
        const int d = ei[TOT_E + eg] - base;
        const float2 ea = *(const float2*)&edge_attr[2 * eg];
        atomicAdd(&CT[s * 64 + d], 1.0f);
        atomicAdd(&sea0[d], ea.x);
        atomicAdd(&sea1[d], ea.y);
    }
    __syncthreads();

    const int tx = t & 15, ty = t >> 4;
    const int ci = tx * 4, dt = ty * 4;
    float acc[4][4];
    float dega[4] = {0.f, 0.f, 0.f, 0.f};
#pragma unroll
    for (int j = 0; j < 4; j++) {
        float4 v = *(const float4*)&g_xs[(base + dt + j) * 64 + ci];
        acc[j][0] = v.x; acc[j][1] = v.y; acc[j][2] = v.z; acc[j][3] = v.w;
    }
#pragma unroll 8
    for (int s = 0; s < 64; s++) {
        const float4 cv = *(const float4*)&CT[s * 64 + dt];
        const float4 xv = *(const float4*)&XM[s * 64 + ci];
        const float cj[4] = {cv.x, cv.y, cv.z, cv.w};
#pragma unroll
        for (int j = 0; j < 4; j++) {
            acc[j][0] += cj[j] * xv.x;
            acc[j][1] += cj[j] * xv.y;
            acc[j][2] += cj[j] * xv.z;
            acc[j][3] += cj[j] * xv.w;
            dega[j]   += cj[j];
        }
    }

#pragma unroll
    for (int j = 0; j < 4; j++) {
        const int d = dt + j;
        const unsigned mw = g_mask[(unsigned)(base + d) * 2u + (unsigned)(ci >> 5)];
        const float e0 = sea0[d], e1 = sea1[d], dg = dega[j];
        float4 o;
        float* op = (float*)&o;
#pragma unroll
        for (int k = 0; k < 4; k++) {
            const int c = ci + k;
            float val = acc[j][k] + e0 * sWe0[c] + e1 * sWe1[c] + dg * sbc[c];
            val = fmaxf(val, 0.f);
            val = ((mw >> (c & 31)) & 1u) ? val * 2.0f : 0.f;
            op[k] = val;
        }
        *(float4*)&g_states[b * STATE_W + d * 64 + ci] = o;
    }
}

// ================== tensor-core GEMM (bf16 3-MMA compensated) ==============
// C[M,N] = act(A[M,K] @ B[K,N] + bias), fp32 in/out.
// a = a_hi + a_lo (bf16 split); acc += Ah*Bh + Ah*Bl + Al*Bh  (fp32 accum)
// CTA tile 128x64, 8 warps (4x2), warp tile 32x32, k-tile 32.
// Requires K%32==0, N%64==0, M%128==0.

#define LDSM_X4(r0, r1, r2, r3, addr)                                        \
    asm volatile("ldmatrix.sync.aligned.m8n8.x4.shared.b16 {%0,%1,%2,%3}, [%4];" \
                 : "=r"(r0), "=r"(r1), "=r"(r2), "=r"(r3) : "r"(addr))

#define LDSM_X4_T(r0, r1, r2, r3, addr)                                      \
    asm volatile("ldmatrix.sync.aligned.m8n8.x4.trans.shared.b16 {%0,%1,%2,%3}, [%4];" \
                 : "=r"(r0), "=r"(r1), "=r"(r2), "=r"(r3) : "r"(addr))

#define MMA_BF16(d, a, b0, b1)                                               \
    asm volatile("mma.sync.aligned.m16n8k16.row.col.f32.bf16.bf16.f32 "      \
                 "{%0,%1,%2,%3}, {%4,%5,%6,%7}, {%8,%9}, {%0,%1,%2,%3};"     \
                 : "+f"(d[0]), "+f"(d[1]), "+f"(d[2]), "+f"(d[3])            \
                 : "r"(a[0]), "r"(a[1]), "r"(a[2]), "r"(a[3]),               \
                   "r"(b0), "r"(b1))

#define A_STRIDE 40   // bf16 elems per row (32 + 8 pad) -> 80B, 16B aligned
#define B_STRIDE 72   // bf16 elems per row (64 + 8 pad) -> 144B, 16B aligned

__global__ void __launch_bounds__(256) gemm_mma_kernel(
    const float* __restrict__ A, const float* __restrict__ Bw,
    const float* __restrict__ bias, float* __restrict__ C,
    int K, int Ntot, int do_relu) {
    __shared__ __align__(16) __nv_bfloat16 sAhi[128 * A_STRIDE];
    __shared__ __align__(16) __nv_bfloat16 sAlo[128 * A_STRIDE];
    __shared__ __align__(16) __nv_bfloat16 sBhi[32 * B_STRIDE];
    __shared__ __align__(16) __nv_bfloat16 sBlo[32 * B_STRIDE];

    const int t = threadIdx.x;
    const int lane = t & 31;
    const int warp = t >> 5;
    const int wm = warp & 3;            // 0..3 -> M offset wm*32
    const int wn = warp >> 2;           // 0..1 -> N offset wn*32
    const int row0 = blockIdx.x * 128;
    const int c0 = blockIdx.y * 64;

    // ---- staging assignments
    const int arow = t >> 1, acol = (t & 1) * 16;   // A: 128 rows x 32 k
    const int brow = t >> 3, bcol = (t & 7) * 8;    // B: 32 k x 64 n

    const float* Ap = A + (size_t)(row0 + arow) * K + acol;
    const float* Bp = Bw + (size_t)brow * Ntot + c0 + bcol;

    // ---- ldmatrix shared addresses (byte offsets precomputed)
    const unsigned uAhi = (unsigned)__cvta_generic_to_shared(sAhi);
    const unsigned uAlo = (unsigned)__cvta_generic_to_shared(sAlo);
    const unsigned uBhi = (unsigned)__cvta_generic_to_shared(sBhi);
    const unsigned uBlo = (unsigned)__cvta_generic_to_shared(sBlo);

    // A frag addr (per m-tile mi, k-step ks): row = wm*32+mi*16+(lane&15),
    // col = ks*16 + (lane>>4)*8
    unsigned aoff[2];
#pragma unroll
    for (int mi = 0; mi < 2; mi++)
        aoff[mi] = ((wm * 32 + mi * 16 + (lane & 15)) * A_STRIDE +
                    (lane >> 4) * 8) * 2;
    // B frag addr (per col-group g, k-step ks):
    // row = ks*16 + ((lane>>3)&1)*8 + (lane&7), col = wn*32 + g*16 + (lane>>4)*8
    unsigned boff[2];
#pragma unroll
    for (int g = 0; g < 2; g++)
        boff[g] = ((((lane >> 3) & 1) * 8 + (lane & 7)) * B_STRIDE +
                   wn * 32 + g * 16 + (lane >> 4) * 8) * 2;

    float acc[2][4][4];
#pragma unroll
    for (int mi = 0; mi < 2; mi++)
#pragma unroll
        for (int nj = 0; nj < 4; nj++)
#pragma unroll
            for (int i = 0; i < 4; i++) acc[mi][nj][i] = 0.f;

    // ---- prologue: load k-tile 0 into registers
    float4 ar[4], br[2];
#pragma unroll
    for (int i = 0; i < 4; i++) ar[i] = *(const float4*)&Ap[i * 4];
#pragma unroll
    for (int i = 0; i < 2; i++) br[i] = *(const float4*)&Bp[i * 4];

    const int nk = K / 32;
    for (int kt = 0; kt < nk; kt++) {
        __syncthreads();
        // ---- stage: split fp32 -> (bf16 hi, bf16 lo), store to SMEM
        {
            const float* av = (const float*)ar;
#pragma unroll
            for (int j = 0; j < 8; j++) {
                float v0 = av[2 * j], v1 = av[2 * j + 1];
                __nv_bfloat16 h0 = __float2bfloat16(v0);
                __nv_bfloat16 h1 = __float2bfloat16(v1);
                __nv_bfloat16 l0 = __float2bfloat16(v0 - __bfloat162float(h0));
                __nv_bfloat16 l1 = __float2bfloat16(v1 - __bfloat162float(h1));
                const int idx = arow * A_STRIDE + acol + 2 * j;
                *(__nv_bfloat162*)&sAhi[idx] = __nv_bfloat162(h0, h1);
                *(__nv_bfloat162*)&sAlo[idx] = __nv_bfloat162(l0, l1);
            }
            const float* bv = (const float*)br;
#pragma unroll
            for (int j = 0; j < 4; j++) {
                float v0 = bv[2 * j], v1 = bv[2 * j + 1];
                __nv_bfloat16 h0 = __float2bfloat16(v0);
                __nv_bfloat16 h1 = __float2bfloat16(v1);
                __nv_bfloat16 l0 = __float2bfloat16(v0 - __bfloat162float(h0));
                __nv_bfloat16 l1 = __float2bfloat16(v1 - __bfloat162float(h1));
                const int idx = brow * B_STRIDE + bcol + 2 * j;
                *(__nv_bfloat162*)&sBhi[idx] = __nv_bfloat162(h0, h1);
                *(__nv_bfloat162*)&sBlo[idx] = __nv_bfloat162(l0, l1);
            }
        }
        __syncthreads();

        // ---- prefetch next k-tile (LDG latency overlaps compute below)
        if (kt + 1 < nk) {
            const float* An = Ap + (kt + 1) * 32;
            const float* Bn = Bp + (size_t)(kt + 1) * 32 * Ntot;
#pragma unroll
            for (int i = 0; i < 4; i++) ar[i] = *(const float4*)&An[i * 4];
#pragma unroll
            for (int i = 0; i < 2; i++) br[i] = *(const float4*)&Bn[i * 4];
        }

        // ---- compute: 2 k-steps of 16
#pragma unroll
        for (int ks = 0; ks < 2; ks++) {
            unsigned ah[2][4], al[2][4];
#pragma unroll
            for (int mi = 0; mi < 2; mi++) {
                LDSM_X4(ah[mi][0], ah[mi][1], ah[mi][2], ah[mi][3],
                        uAhi + aoff[mi] + ks * 32);
                LDSM_X4(al[mi][0], al[mi][1], al[mi][2], al[mi][3],
                        uAlo + aoff[mi] + ks * 32);
            }
            unsigned bh[2][4], bl[2][4];
#pragma unroll
            for (int g = 0; g < 2; g++) {
                LDSM_X4_T(bh[g][0], bh[g][1], bh[g][2], bh[g][3],
                          uBhi + boff[g] + ks * (16 * B_STRIDE * 2));
                LDSM_X4_T(bl[g][0], bl[g][1], bl[g][2], bl[g][3],
                          uBlo + boff[g] + ks * (16 * B_STRIDE * 2));
            }
#pragma unroll
            for (int mi = 0; mi < 2; mi++)
#pragma unroll
                for (int nj = 0; nj < 4; nj++) {
                    const int g = nj >> 1, o = (nj & 1) * 2;
                    MMA_BF16(acc[mi][nj], ah[mi], bh[g][o], bh[g][o + 1]);
                    MMA_BF16(acc[mi][nj], ah[mi], bl[g][o], bl[g][o + 1]);
                    MMA_BF16(acc[mi][nj], al[mi], bh[g][o], bh[g][o + 1]);
                }
        }
    }

    // ---- epilogue: bias + optional relu, fp32 stores
    const int erow = lane >> 2;          // 0..7
    const int ecol = (lane & 3) * 2;     // 0,2,4,6
#pragma unroll
    for (int nj = 0; nj < 4; nj++) {
        const int c = c0 + wn * 32 + nj * 8 + ecol;
        const float bz0 = bias[c], bz1 = bias[c + 1];
#pragma unroll
        for (int mi = 0; mi < 2; mi++) {
            const int r = row0 + wm * 32 + mi * 16 + erow;
            float v0 = acc[mi][nj][0] + bz0;
            float v1 = acc[mi][nj][1] + bz1;
            float v2 = acc[mi][nj][2] + bz0;
            float v3 = acc[mi][nj][3] + bz1;
            if (do_relu) {
                v0 = fmaxf(v0, 0.f); v1 = fmaxf(v1, 0.f);
                v2 = fmaxf(v2, 0.f); v3 = fmaxf(v3, 0.f);
            }
            *(float2*)&C[(size_t)r * Ntot + c] = make_float2(v0, v1);
            *(float2*)&C[(size_t)(r + 8) * Ntot + c] = make_float2(v2, v3);
        }
    }
}

// ---------------- softmax across the batch axis (column-wise) --------------
__global__ void __launch_bounds__(256) softmax_kernel(float* __restrict__ out) {
    const int c = blockIdx.x;        // column 0..63
    const int t = threadIdx.x;
    const int lane = t & 31, wid = t >> 5;
    __shared__ float redm[8];
    __shared__ float reds[8];

    float v[8];
    float mx = -1e30f;
#pragma unroll
    for (int i = 0; i < 8; i++) {
        v[i] = g_logits[(i * 256 + t) * 64 + c];
        mx = fmaxf(mx, v[i]);
    }
#pragma unroll
    for (int o = 16; o; o >>= 1) mx = fmaxf(mx, __shfl_xor_sync(~0u, mx, o));
    if (lane == 0) redm[wid] = mx;
    __syncthreads();
    mx = redm[0];
#pragma unroll
    for (int w = 1; w < 8; w++) mx = fmaxf(mx, redm[w]);

    float sum = 0.f;
#pragma unroll
    for (int i = 0; i < 8; i++) { v[i] = expf(v[i] - mx); sum += v[i]; }
#pragma unroll
    for (int o = 16; o; o >>= 1) sum += __shfl_xor_sync(~0u, sum, o);
    if (lane == 0) reds[wid] = sum;
    __syncthreads();
    sum = 0.f;
#pragma unroll
    for (int w = 0; w < 8; w++) sum += reds[w];
    const float inv = 1.0f / sum;

#pragma unroll
    for (int i = 0; i < 8; i++) out[(i * 256 + t) * 64 + c] = v[i] * inv;
}

// ---------------------------------------------------------------------------
extern "C" void kernel_launch(void* const* d_in, const int* in_sizes, int n_in,
                              void* d_out, int out_size) {
    const float* x         = (const float*)d_in[0];
    const float* edge_attr = (const float*)d_in[1];
    const float* user_s    = (const float*)d_in[2];
    const float* W_msg     = (const float*)d_in[3];
    const float* b_msg     = (const float*)d_in[4];
    const float* W_edge    = (const float*)d_in[5];
    const float* b_edge    = (const float*)d_in[6];
    const float* W_self    = (const float*)d_in[7];
    const float* b_self    = (const float*)d_in[8];
    const float* W1        = (const float*)d_in[9];
    const float* b1        = (const float*)d_in[10];
    const float* W2        = (const float*)d_in[11];
    const float* b2        = (const float*)d_in[12];
    const float* W3        = (const float*)d_in[13];
    const float* b3        = (const float*)d_in[14];
    const float* W4        = (const float*)d_in[15];
    const float* b4        = (const float*)d_in[16];
    const int*   ei        = (const int*)d_in[17];
    float* out = (float*)d_out;

    float *states, *h1, *h2, *logits;
    cudaGetSymbolAddress((void**)&states, g_states);
    cudaGetSymbolAddress((void**)&h1, g_h1);
    cudaGetSymbolAddress((void**)&h2, g_h2);
    cudaGetSymbolAddress((void**)&logits, g_logits);

    mask_kernel<<<MASK_N / 256, 256>>>();
    xw_kernel<<<TOT_N / 64, 256>>>(x, W_msg, W_self, b_self);
    node_kernel<<<B_GR, 256>>>(edge_attr, ei, W_edge, b_msg, b_edge,
                               user_s, W1, b1);
    gemm_mma_kernel<<<dim3(B_GR / 128, HID / 64), 256>>>(
        states, W2, b2, h1, STATE_W, HID, 1);
    gemm_mma_kernel<<<dim3(B_GR / 128, (HID / 2) / 64), 256>>>(
        h1, W3, b3, h2, HID, HID / 2, 1);
    gemm_mma_kernel<<<dim3(B_GR / 128, N_NODE / 64), 256>>>(
        h2, W4, b4, logits, HID / 2, N_NODE, 0);
    softmax_kernel<<<N_NODE, 256>>>(out);
}

// round 14
// speedup vs baseline: 1.8769x; 1.1938x over previous
#include <cuda_runtime.h>
#include <cuda_bf16.h>
#include <cstdint>

#define B_GR   2048
#define N_NODE 64
#define E_PG   512
#define TOT_N  (B_GR * N_NODE)     // 131072
#define TOT_E  (B_GR * E_PG)       // 1048576
#define D_EMB  64
#define STATE_W 4160               // 64*64 + 64
#define HID    512
#define MASK_N 8388608u            // TOT_N * D_EMB

// ---------------- scratch (static device arrays; no runtime alloc) ---------
__device__ float          g_xm[TOT_N * D_EMB];
__device__ float          g_xs[TOT_N * D_EMB];
__device__ __nv_bfloat16  g_st_hi[B_GR * STATE_W];
__device__ __nv_bfloat16  g_st_lo[B_GR * STATE_W];
__device__ __nv_bfloat16  g_h1_hi[B_GR * HID];
__device__ __nv_bfloat16  g_h1_lo[B_GR * HID];
__device__ __nv_bfloat16  g_h2_hi[B_GR * (HID / 2)];
__device__ __nv_bfloat16  g_h2_lo[B_GR * (HID / 2)];
__device__ __nv_bfloat16  g_w2_hi[STATE_W * HID];
__device__ __nv_bfloat16  g_w2_lo[STATE_W * HID];
__device__ __nv_bfloat16  g_w3_hi[HID * (HID / 2)];
__device__ __nv_bfloat16  g_w3_lo[HID * (HID / 2)];
__device__ __nv_bfloat16  g_w4_hi[(HID / 2) * N_NODE];
__device__ __nv_bfloat16  g_w4_lo[(HID / 2) * N_NODE];
__device__ float          g_logits[B_GR * N_NODE];
__device__ unsigned       g_mask[MASK_N / 32];

// ------- threefry-2x32 dropout mask, JAX partitionable path, key 42 --------
__device__ __forceinline__ unsigned rotl32(unsigned v, int s) {
    return (v << s) | (v >> (32 - s));
}

__global__ void __launch_bounds__(256) mask_kernel() {
    unsigned i = blockIdx.x * 256u + threadIdx.x;
    unsigned x0 = 0u, x1 = i;
    const unsigned k0 = 0u, k1 = 42u, k2 = 0x1BD11BDAu ^ k0 ^ k1;
#define TF4(a, b, c, d)                                  \
    x0 += x1; x1 = rotl32(x1, a); x1 ^= x0;              \
    x0 += x1; x1 = rotl32(x1, b); x1 ^= x0;              \
    x0 += x1; x1 = rotl32(x1, c); x1 ^= x0;              \
    x0 += x1; x1 = rotl32(x1, d); x1 ^= x0;
    x0 += k0; x1 += k1;
    TF4(13, 15, 26, 6)  x0 += k1; x1 += k2 + 1u;
    TF4(17, 29, 16, 24) x0 += k2; x1 += k0 + 2u;
    TF4(13, 15, 26, 6)  x0 += k0; x1 += k1 + 3u;
    TF4(17, 29, 16, 24) x0 += k1; x1 += k2 + 4u;
    TF4(13, 15, 26, 6)  x0 += k2; x1 += k0 + 5u;
#undef TF4
    const unsigned bits = x0 ^ x1;
    unsigned w = __ballot_sync(0xffffffffu, (bits >> 31) == 0u);
    if ((threadIdx.x & 31u) == 0u) g_mask[i >> 5] = w;
}

// ---------------- xm = x @ W_msg ; xs = x @ W_self + b_self ----------------
__global__ void __launch_bounds__(256) xw_kernel(
    const float* __restrict__ x, const float* __restrict__ Wm,
    const float* __restrict__ Ws, const float* __restrict__ bs) {
    __shared__ float sx[64 * 16];
    const int t = threadIdx.x;
    const int row0 = blockIdx.x * 64;
#pragma unroll
    for (int i = 0; i < 4; i++) sx[t + i * 256] = x[row0 * 16 + t + i * 256];

    const int c = t & 63, rl = t >> 6;
    float wm[16], ws[16];
#pragma unroll
    for (int k = 0; k < 16; k++) { wm[k] = Wm[k * 64 + c]; ws[k] = Ws[k * 64 + c]; }
    const float bsc = bs[c];
    __syncthreads();

#pragma unroll 4
    for (int q = 0; q < 16; q++) {
        const int r = rl * 16 + q;
        const float4* xr = (const float4*)&sx[r * 16];
        float4 a0 = xr[0], a1 = xr[1], a2 = xr[2], a3 = xr[3];
        float xk[16] = {a0.x, a0.y, a0.z, a0.w, a1.x, a1.y, a1.z, a1.w,
                        a2.x, a2.y, a2.z, a2.w, a3.x, a3.y, a3.z, a3.w};
        float sm = 0.f, ss = 0.f;
#pragma unroll
        for (int k = 0; k < 16; k++) { sm += xk[k] * wm[k]; ss += xk[k] * ws[k]; }
        const int row = row0 + r;
        g_xm[row * 64 + c] = sm;
        g_xs[row * 64 + c] = ss + bsc;
    }
}

// ---------------- fp32 -> (bf16 hi, bf16 lo) weight splitter ---------------
__global__ void __launch_bounds__(256) split_kernel(
    const float* __restrict__ w, __nv_bfloat16* __restrict__ hi,
    __nv_bfloat16* __restrict__ lo, int n) {
    int i = blockIdx.x * 256 + threadIdx.x;
    if (i < n) {
        float v = w[i];
        __nv_bfloat16 h = __float2bfloat16(v);
        hi[i] = h;
        lo[i] = __float2bfloat16(v - __bfloat162float(h));
    }
}

// ------- per-graph: edge scan + dense 64^3 aggregation + relu/dropout ------
// writes states as bf16 hi/lo pairs (GEMM1 A operand)
__global__ void __launch_bounds__(256) node_kernel(
    const float* __restrict__ edge_attr, const int* __restrict__ ei,
    const float* __restrict__ W_edge, const float* __restrict__ b_msg,
    const float* __restrict__ b_edge, const float* __restrict__ user_s,
    const float* __restrict__ W1, const float* __restrict__ b1) {
    __shared__ float CT[64 * 64];
    __shared__ float XM[64 * 64];
    __shared__ float sea0[64], sea1[64];
    __shared__ float sWe0[64], sWe1[64], sbc[64];

    const int t = threadIdx.x;
    const int b = blockIdx.x;
    const int base = b * 64;

#pragma unroll
    for (int i = 0; i < 16; i++) CT[t + i * 256] = 0.f;
    if (t < 64) {
        sea0[t] = 0.f; sea1[t] = 0.f;
        sWe0[t] = W_edge[t]; sWe1[t] = W_edge[64 + t];
        sbc[t] = b_msg[t] + b_edge[t];
    }
    {
        const float4* xmg = (const float4*)&g_xm[base * 64];
        float4* xms = (float4*)XM;
#pragma unroll
        for (int i = 0; i < 4; i++) xms[t + i * 256] = xmg[t + i * 256];
    }
    if (t < 64) {   // user = relu(user_s[b] @ W1 + b1) -> states hi/lo
        float u = b1[t];
#pragma unroll
        for (int k = 0; k < 32; k++) u += user_s[b * 32 + k] * W1[k * 64 + t];
        u = fmaxf(u, 0.f);
        __nv_bfloat16 h = __float2bfloat16(u);
        g_st_hi[b * STATE_W + 4096 + t] = h;
        g_st_lo[b * STATE_W + 4096 + t] =
            __float2bfloat16(u - __bfloat162float(h));
    }
    __syncthreads();

#pragma unroll
    for (int i = 0; i < 2; i++) {
        const int e = t + i * 256;
        const int eg = b * E_PG + e;
        const int s = ei[eg] - base;
        const int d = ei[TOT_E + eg] - base;
        const float2 ea = *(const float2*)&edge_attr[2 * eg];
        atomicAdd(&CT[s * 64 + d], 1.0f);
        atomicAdd(&sea0[d], ea.x);
        atomicAdd(&sea1[d], ea.y);
    }
    __syncthreads();

    const int tx = t & 15, ty = t >> 4;
    const int ci = tx * 4, dt = ty * 4;
    float acc[4][4];
    float dega[4] = {0.f, 0.f, 0.f, 0.f};
#pragma unroll
    for (int j = 0; j < 4; j++) {
        float4 v = *(const float4*)&g_xs[(base + dt + j) * 64 + ci];
        acc[j][0] = v.x; acc[j][1] = v.y; acc[j][2] = v.z; acc[j][3] = v.w;
    }
#pragma unroll 8
    for (int s = 0; s < 64; s++) {
        const float4 cv = *(const float4*)&CT[s * 64 + dt];
        const float4 xv = *(const float4*)&XM[s * 64 + ci];
        const float cj[4] = {cv.x, cv.y, cv.z, cv.w};
#pragma unroll
        for (int j = 0; j < 4; j++) {
            acc[j][0] += cj[j] * xv.x;
            acc[j][1] += cj[j] * xv.y;
            acc[j][2] += cj[j] * xv.z;
            acc[j][3] += cj[j] * xv.w;
            dega[j]   += cj[j];
        }
    }

#pragma unroll
    for (int j = 0; j < 4; j++) {
        const int d = dt + j;
        const unsigned mw = g_mask[(unsigned)(base + d) * 2u + (unsigned)(ci >> 5)];
        const float e0 = sea0[d], e1 = sea1[d], dg = dega[j];
        __nv_bfloat16 hv[4], lv[4];
#pragma unroll
        for (int k = 0; k < 4; k++) {
            const int c = ci + k;
            float val = acc[j][k] + e0 * sWe0[c] + e1 * sWe1[c] + dg * sbc[c];
            val = fmaxf(val, 0.f);
            val = ((mw >> (c & 31)) & 1u) ? val * 2.0f : 0.f;
            __nv_bfloat16 h = __float2bfloat16(val);
            hv[k] = h;
            lv[k] = __float2bfloat16(val - __bfloat162float(h));
        }
        const int idx = b * STATE_W + d * 64 + ci;
        *(__nv_bfloat162*)&g_st_hi[idx]     = __nv_bfloat162(hv[0], hv[1]);
        *(__nv_bfloat162*)&g_st_hi[idx + 2] = __nv_bfloat162(hv[2], hv[3]);
        *(__nv_bfloat162*)&g_st_lo[idx]     = __nv_bfloat162(lv[0], lv[1]);
        *(__nv_bfloat162*)&g_st_lo[idx + 2] = __nv_bfloat162(lv[2], lv[3]);
    }
}

// =========== async double-buffered tensor-core GEMM (bf16 3-MMA) ===========
// C = act(A @ B + bias); A,B pre-split into bf16 hi/lo.
// CTA 128x64, 8 warps (4x2), warp tile 32x32, k-tile 32, 2 cp.async stages.

#define LDSM_X4(r0, r1, r2, r3, addr)                                        \
    asm volatile("ldmatrix.sync.aligned.m8n8.x4.shared.b16 {%0,%1,%2,%3}, [%4];" \
                 : "=r"(r0), "=r"(r1), "=r"(r2), "=r"(r3) : "r"(addr))

#define LDSM_X4_T(r0, r1, r2, r3, addr)                                      \
    asm volatile("ldmatrix.sync.aligned.m8n8.x4.trans.shared.b16 {%0,%1,%2,%3}, [%4];" \
                 : "=r"(r0), "=r"(r1), "=r"(r2), "=r"(r3) : "r"(addr))

#define MMA_BF16(d, a, b0, b1)                                               \
    asm volatile("mma.sync.aligned.m16n8k16.row.col.f32.bf16.bf16.f32 "      \
                 "{%0,%1,%2,%3}, {%4,%5,%6,%7}, {%8,%9}, {%0,%1,%2,%3};"     \
                 : "+f"(d[0]), "+f"(d[1]), "+f"(d[2]), "+f"(d[3])            \
                 : "r"(a[0]), "r"(a[1]), "r"(a[2]), "r"(a[3]),               \
                   "r"(b0), "r"(b1))

#define CP16(dst, src)                                                       \
    asm volatile("cp.async.cg.shared.global [%0], [%1], 16;" ::              \
                 "r"(dst), "l"(src))
#define CP_COMMIT() asm volatile("cp.async.commit_group;")
#define CP_WAIT1()  asm volatile("cp.async.wait_group 1;")
#define CP_WAIT0()  asm volatile("cp.async.wait_group 0;")

#define A_STRIDE 40            // elems: 32 + 8 pad (80 B rows, 16B-aligned)
#define B_STRIDE 72            // elems: 64 + 8 pad (144 B rows)
#define OFF_ALO  10240         // 128 * 80
#define OFF_BHI  20480
#define OFF_BLO  25088         // + 32 * 144
#define STAGE_B  29696         // total stage bytes
#define SMEM_TOT (2 * STAGE_B) // 59392

__global__ void __launch_bounds__(256) gemm_mma_async(
    const __nv_bfloat16* __restrict__ Ahi, const __nv_bfloat16* __restrict__ Alo,
    const __nv_bfloat16* __restrict__ Bhi, const __nv_bfloat16* __restrict__ Blo,
    const float* __restrict__ bias,
    __nv_bfloat16* __restrict__ Chi, __nv_bfloat16* __restrict__ Clo,
    float* __restrict__ Cf,
    int K, int Ntot, int do_relu) {
    extern __shared__ __align__(16) char smem[];

    const int t = threadIdx.x;
    const int lane = t & 31;
    const int warp = t >> 5;
    const int wm = warp & 3;
    const int wn = warp >> 2;
    const int row0 = blockIdx.x * 128;
    const int c0 = blockIdx.y * 64;

    // staging: A 128 rows x 32k, thread -> row=t>>1, col base (t&1)*16
    const int arow = t >> 1, acol = (t & 1) * 16;
    const int brow = t >> 3, bcol = (t & 7) * 8;

    const size_t a_base = (size_t)(row0 + arow) * K + acol;
    const size_t b_base = (size_t)brow * Ntot + c0 + bcol;
    const unsigned a_dst = arow * 80 + acol * 2;
    const unsigned b_dst = brow * 144 + bcol * 2;

    unsigned u0;
    { unsigned tmp = (unsigned)__cvta_generic_to_shared(smem); u0 = tmp; }

    // ldmatrix fragment offsets (within a stage)
    unsigned aoff[2];
#pragma unroll
    for (int mi = 0; mi < 2; mi++)
        aoff[mi] = ((wm * 32 + mi * 16 + (lane & 15)) * A_STRIDE +
                    (lane >> 4) * 8) * 2;
    unsigned boff[2];
#pragma unroll
    for (int g = 0; g < 2; g++)
        boff[g] = ((((lane >> 3) & 1) * 8 + (lane & 7)) * B_STRIDE +
                   wn * 32 + g * 16 + (lane >> 4) * 8) * 2;

    float acc[2][4][4];
#pragma unroll
    for (int mi = 0; mi < 2; mi++)
#pragma unroll
        for (int nj = 0; nj < 4; nj++)
#pragma unroll
            for (int i = 0; i < 4; i++) acc[mi][nj][i] = 0.f;

    const int nk = K / 32;

    // prologue: stage 0 <- tile 0
    {
        const unsigned s = u0;
        CP16(s + a_dst,                Ahi + a_base);
        CP16(s + a_dst + 16,           Ahi + a_base + 8);
        CP16(s + OFF_ALO + a_dst,      Alo + a_base);
        CP16(s + OFF_ALO + a_dst + 16, Alo + a_base + 8);
        CP16(s + OFF_BHI + b_dst,      Bhi + b_base);
        CP16(s + OFF_BLO + b_dst,      Blo + b_base);
        CP_COMMIT();
    }

    for (int kt = 0; kt < nk; kt++) {
        __syncthreads();   // buffer (kt+1)&1 free of readers from iter kt-1
        if (kt + 1 < nk) {
            const unsigned s = u0 + ((kt + 1) & 1) * STAGE_B;
            const size_t aoe = a_base + (size_t)(kt + 1) * 32;
            const size_t boe = b_base + (size_t)(kt + 1) * 32 * Ntot;
            CP16(s + a_dst,                Ahi + aoe);
            CP16(s + a_dst + 16,           Ahi + aoe + 8);
            CP16(s + OFF_ALO + a_dst,      Alo + aoe);
            CP16(s + OFF_ALO + a_dst + 16, Alo + aoe + 8);
            CP16(s + OFF_BHI + b_dst,      Bhi + boe);
            CP16(s + OFF_BLO + b_dst,      Blo + boe);
            CP_COMMIT();
            CP_WAIT1();   // tile kt's group complete
        } else {
            CP_WAIT0();
        }
        __syncthreads();  // tile kt visible to all warps

        const unsigned sb = u0 + (kt & 1) * STAGE_B;
#pragma unroll
        for (int ks = 0; ks < 2; ks++) {
            unsigned ah[2][4], al[2][4];
#pragma unroll
            for (int mi = 0; mi < 2; mi++) {
                LDSM_X4(ah[mi][0], ah[mi][1], ah[mi][2], ah[mi][3],
                        sb + aoff[mi] + ks * 32);
                LDSM_X4(al[mi][0], al[mi][1], al[mi][2], al[mi][3],
                        sb + OFF_ALO + aoff[mi] + ks * 32);
            }
            unsigned bh[2][4], bl[2][4];
#pragma unroll
            for (int g = 0; g < 2; g++) {
                LDSM_X4_T(bh[g][0], bh[g][1], bh[g][2], bh[g][3],
                          sb + OFF_BHI + boff[g] + ks * (16 * B_STRIDE * 2));
                LDSM_X4_T(bl[g][0], bl[g][1], bl[g][2], bl[g][3],
                          sb + OFF_BLO + boff[g] + ks * (16 * B_STRIDE * 2));
            }
#pragma unroll
            for (int mi = 0; mi < 2; mi++)
#pragma unroll
                for (int nj = 0; nj < 4; nj++) {
                    const int g = nj >> 1, o = (nj & 1) * 2;
                    MMA_BF16(acc[mi][nj], ah[mi], bh[g][o], bh[g][o + 1]);
                    MMA_BF16(acc[mi][nj], ah[mi], bl[g][o], bl[g][o + 1]);
                    MMA_BF16(acc[mi][nj], al[mi], bh[g][o], bh[g][o + 1]);
                }
        }
    }

    // ---- epilogue: bias + relu, then fp32 OR bf16 hi/lo stores
    const int erow = lane >> 2;
    const int ecol = (lane & 3) * 2;
#pragma unroll
    for (int nj = 0; nj < 4; nj++) {
        const int c = c0 + wn * 32 + nj * 8 + ecol;
        const float bz0 = bias[c], bz1 = bias[c + 1];
#pragma unroll
        for (int mi = 0; mi < 2; mi++) {
            const int r = row0 + wm * 32 + mi * 16 + erow;
            float v0 = acc[mi][nj][0] + bz0;
            float v1 = acc[mi][nj][1] + bz1;
            float v2 = acc[mi][nj][2] + bz0;
            float v3 = acc[mi][nj][3] + bz1;
            if (do_relu) {
                v0 = fmaxf(v0, 0.f); v1 = fmaxf(v1, 0.f);
                v2 = fmaxf(v2, 0.f); v3 = fmaxf(v3, 0.f);
            }
            if (Cf) {
                *(float2*)&Cf[(size_t)r * Ntot + c] = make_float2(v0, v1);
                *(float2*)&Cf[(size_t)(r + 8) * Ntot + c] = make_float2(v2, v3);
            } else {
                __nv_bfloat16 h0 = __float2bfloat16(v0);
                __nv_bfloat16 h1 = __float2bfloat16(v1);
                __nv_bfloat16 h2 = __float2bfloat16(v2);
                __nv_bfloat16 h3 = __float2bfloat16(v3);
                *(__nv_bfloat162*)&Chi[(size_t)r * Ntot + c] =
                    __nv_bfloat162(h0, h1);
                *(__nv_bfloat162*)&Chi[(size_t)(r + 8) * Ntot + c] =
                    __nv_bfloat162(h2, h3);
                *(__nv_bfloat162*)&Clo[(size_t)r * Ntot + c] = __nv_bfloat162(
                    __float2bfloat16(v0 - __bfloat162float(h0)),
                    __float2bfloat16(v1 - __bfloat162float(h1)));
                *(__nv_bfloat162*)&Clo[(size_t)(r + 8) * Ntot + c] =
                    __nv_bfloat162(
                        __float2bfloat16(v2 - __bfloat162float(h2)),
                        __float2bfloat16(v3 - __bfloat162float(h3)));
            }
        }
    }
}

// ---------------- softmax across the batch axis (column-wise) --------------
__global__ void __launch_bounds__(256) softmax_kernel(float* __restrict__ out) {
    const int c = blockIdx.x;
    const int t = threadIdx.x;
    const int lane = t & 31, wid = t >> 5;
    __shared__ float redm[8];
    __shared__ float reds[8];

    float v[8];
    float mx = -1e30f;
#pragma unroll
    for (int i = 0; i < 8; i++) {
        v[i] = g_logits[(i * 256 + t) * 64 + c];
        mx = fmaxf(mx, v[i]);
    }
#pragma unroll
    for (int o = 16; o; o >>= 1) mx = fmaxf(mx, __shfl_xor_sync(~0u, mx, o));
    if (lane == 0) redm[wid] = mx;
    __syncthreads();
    mx = redm[0];
#pragma unroll
    for (int w = 1; w < 8; w++) mx = fmaxf(mx, redm[w]);

    float sum = 0.f;
#pragma unroll
    for (int i = 0; i < 8; i++) { v[i] = expf(v[i] - mx); sum += v[i]; }
#pragma unroll
    for (int o = 16; o; o >>= 1) sum += __shfl_xor_sync(~0u, sum, o);
    if (lane == 0) reds[wid] = sum;
    __syncthreads();
    sum = 0.f;
#pragma unroll
    for (int w = 0; w < 8; w++) sum += reds[w];
    const float inv = 1.0f / sum;

#pragma unroll
    for (int i = 0; i < 8; i++) out[(i * 256 + t) * 64 + c] = v[i] * inv;
}

// ---------------------------------------------------------------------------
extern "C" void kernel_launch(void* const* d_in, const int* in_sizes, int n_in,
                              void* d_out, int out_size) {
    const float* x         = (const float*)d_in[0];
    const float* edge_attr = (const float*)d_in[1];
    const float* user_s    = (const float*)d_in[2];
    const float* W_msg     = (const float*)d_in[3];
    const float* b_msg     = (const float*)d_in[4];
    const float* W_edge    = (const float*)d_in[5];
    const float* b_edge    = (const float*)d_in[6];
    const float* W_self    = (const float*)d_in[7];
    const float* b_self    = (const float*)d_in[8];
    const float* W1        = (const float*)d_in[9];
    const float* b1        = (const float*)d_in[10];
    const float* W2        = (const float*)d_in[11];
    const float* b2        = (const float*)d_in[12];
    const float* W3        = (const float*)d_in[13];
    const float* b3        = (const float*)d_in[14];
    const float* W4        = (const float*)d_in[15];
    const float* b4        = (const float*)d_in[16];
    const int*   ei        = (const int*)d_in[17];
    float* out = (float*)d_out;

    // idempotent, host-side, capture-safe — no static guard (harness rule)
    cudaFuncSetAttribute(gemm_mma_async,
                         cudaFuncAttributeMaxDynamicSharedMemorySize,
                         SMEM_TOT);

    __nv_bfloat16 *sthi, *stlo, *h1hi, *h1lo, *h2hi, *h2lo;
    __nv_bfloat16 *w2hi, *w2lo, *w3hi, *w3lo, *w4hi, *w4lo;
    float* logits;
    cudaGetSymbolAddress((void**)&sthi, g_st_hi);
    cudaGetSymbolAddress((void**)&stlo, g_st_lo);
    cudaGetSymbolAddress((void**)&h1hi, g_h1_hi);
    cudaGetSymbolAddress((void**)&h1lo, g_h1_lo);
    cudaGetSymbolAddress((void**)&h2hi, g_h2_hi);
    cudaGetSymbolAddress((void**)&h2lo, g_h2_lo);
    cudaGetSymbolAddress((void**)&w2hi, g_w2_hi);
    cudaGetSymbolAddress((void**)&w2lo, g_w2_lo);
    cudaGetSymbolAddress((void**)&w3hi, g_w3_hi);
    cudaGetSymbolAddress((void**)&w3lo, g_w3_lo);
    cudaGetSymbolAddress((void**)&w4hi, g_w4_hi);
    cudaGetSymbolAddress((void**)&w4lo, g_w4_lo);
    cudaGetSymbolAddress((void**)&logits, g_logits);

    mask_kernel<<<MASK_N / 256, 256>>>();
    xw_kernel<<<TOT_N / 64, 256>>>(x, W_msg, W_self, b_self);
    split_kernel<<<(STATE_W * HID + 255) / 256, 256>>>(W2, w2hi, w2lo,
                                                       STATE_W * HID);
    split_kernel<<<(HID * (HID / 2) + 255) / 256, 256>>>(W3, w3hi, w3lo,
                                                         HID * (HID / 2));
    split_kernel<<<((HID / 2) * N_NODE + 255) / 256, 256>>>(W4, w4hi, w4lo,
                                                            (HID / 2) * N_NODE);
    node_kernel<<<B_GR, 256>>>(edge_attr, ei, W_edge, b_msg, b_edge,
                               user_s, W1, b1);
    gemm_mma_async<<<dim3(B_GR / 128, HID / 64), 256, SMEM_TOT>>>(
        sthi, stlo, w2hi, w2lo, b2, h1hi, h1lo, nullptr, STATE_W, HID, 1);
    gemm_mma_async<<<dim3(B_GR / 128, (HID / 2) / 64), 256, SMEM_TOT>>>(
        h1hi, h1lo, w3hi, w3lo, b3, h2hi, h2lo, nullptr, HID, HID / 2, 1);
    gemm_mma_async<<<dim3(B_GR / 128, N_NODE / 64), 256, SMEM_TOT>>>(
        h2hi, h2lo, w4hi, w4lo, b4, nullptr, nullptr, logits, HID / 2,
        N_NODE, 0);
    softmax_kernel<<<N_NODE, 256>>>(out);
}

// round 16
// speedup vs baseline: 1.9371x; 1.0321x over previous
#include <cuda_runtime.h>
#include <cuda_bf16.h>
#include <cstdint>

#define B_GR   2048
#define N_NODE 64
#define E_PG   512
#define TOT_N  (B_GR * N_NODE)     // 131072
#define TOT_E  (B_GR * E_PG)       // 1048576
#define D_EMB  64
#define STATE_W 4160               // 64*64 + 64
#define HID    512
#define MASK_N 8388608u            // TOT_N * D_EMB

// ---------------- scratch (static device arrays; no runtime alloc) ---------
__device__ float          g_xm[TOT_N * D_EMB];
__device__ float          g_xs[TOT_N * D_EMB];
__device__ __nv_bfloat16  g_st_hi[B_GR * STATE_W];
__device__ __nv_bfloat16  g_st_lo[B_GR * STATE_W];
__device__ __nv_bfloat16  g_h1_hi[B_GR * HID];
__device__ __nv_bfloat16  g_h1_lo[B_GR * HID];
__device__ __nv_bfloat16  g_h2_hi[B_GR * (HID / 2)];
__device__ __nv_bfloat16  g_h2_lo[B_GR * (HID / 2)];
__device__ __nv_bfloat16  g_w2_hi[STATE_W * HID];
__device__ __nv_bfloat16  g_w2_lo[STATE_W * HID];
__device__ __nv_bfloat16  g_w3_hi[HID * (HID / 2)];
__device__ __nv_bfloat16  g_w3_lo[HID * (HID / 2)];
__device__ __nv_bfloat16  g_w4_hi[(HID / 2) * N_NODE];
__device__ __nv_bfloat16  g_w4_lo[(HID / 2) * N_NODE];
__device__ float          g_logits[B_GR * N_NODE];
__device__ unsigned       g_mask[MASK_N / 32];

// ------- threefry-2x32 dropout mask, JAX partitionable path, key 42 --------
__device__ __forceinline__ unsigned rotl32(unsigned v, int s) {
    return (v << s) | (v >> (32 - s));
}

__global__ void __launch_bounds__(256) mask_kernel() {
    unsigned i = blockIdx.x * 256u + threadIdx.x;
    unsigned x0 = 0u, x1 = i;
    const unsigned k0 = 0u, k1 = 42u, k2 = 0x1BD11BDAu ^ k0 ^ k1;
#define TF4(a, b, c, d)                                  \
    x0 += x1; x1 = rotl32(x1, a); x1 ^= x0;              \
    x0 += x1; x1 = rotl32(x1, b); x1 ^= x0;              \
    x0 += x1; x1 = rotl32(x1, c); x1 ^= x0;              \
    x0 += x1; x1 = rotl32(x1, d); x1 ^= x0;
    x0 += k0; x1 += k1;
    TF4(13, 15, 26, 6)  x0 += k1; x1 += k2 + 1u;
    TF4(17, 29, 16, 24) x0 += k2; x1 += k0 + 2u;
    TF4(13, 15, 26, 6)  x0 += k0; x1 += k1 + 3u;
    TF4(17, 29, 16, 24) x0 += k1; x1 += k2 + 4u;
    TF4(13, 15, 26, 6)  x0 += k2; x1 += k0 + 5u;
#undef TF4
    const unsigned bits = x0 ^ x1;
    unsigned w = __ballot_sync(0xffffffffu, (bits >> 31) == 0u);
    if ((threadIdx.x & 31u) == 0u) g_mask[i >> 5] = w;
}

// ---------------- xm = x @ W_msg ; xs = x @ W_self + b_self ----------------
__global__ void __launch_bounds__(256) xw_kernel(
    const float* __restrict__ x, const float* __restrict__ Wm,
    const float* __restrict__ Ws, const float* __restrict__ bs) {
    __shared__ float sx[64 * 16];
    const int t = threadIdx.x;
    const int row0 = blockIdx.x * 64;
#pragma unroll
    for (int i = 0; i < 4; i++) sx[t + i * 256] = x[row0 * 16 + t + i * 256];

    const int c = t & 63, rl = t >> 6;
    float wm[16], ws[16];
#pragma unroll
    for (int k = 0; k < 16; k++) { wm[k] = Wm[k * 64 + c]; ws[k] = Ws[k * 64 + c]; }
    const float bsc = bs[c];
    __syncthreads();

#pragma unroll 4
    for (int q = 0; q < 16; q++) {
        const int r = rl * 16 + q;
        const float4* xr = (const float4*)&sx[r * 16];
        float4 a0 = xr[0], a1 = xr[1], a2 = xr[2], a3 = xr[3];
        float xk[16] = {a0.x, a0.y, a0.z, a0.w, a1.x, a1.y, a1.z, a1.w,
                        a2.x, a2.y, a2.z, a2.w, a3.x, a3.y, a3.z, a3.w};
        float sm = 0.f, ss = 0.f;
#pragma unroll
        for (int k = 0; k < 16; k++) { sm += xk[k] * wm[k]; ss += xk[k] * ws[k]; }
        const int row = row0 + r;
        g_xm[row * 64 + c] = sm;
        g_xs[row * 64 + c] = ss + bsc;
    }
}

// ---------------- fp32 -> (bf16 hi, bf16 lo) weight splitter ---------------
__global__ void __launch_bounds__(256) split_kernel(
    const float* __restrict__ w, __nv_bfloat16* __restrict__ hi,
    __nv_bfloat16* __restrict__ lo, int n) {
    int i = blockIdx.x * 256 + threadIdx.x;
    if (i < n) {
        float v = w[i];
        __nv_bfloat16 h = __float2bfloat16(v);
        hi[i] = h;
        lo[i] = __float2bfloat16(v - __bfloat162float(h));
    }
}

// ------- per-graph: edge scan + dense 64^3 aggregation + relu/dropout ------
__global__ void __launch_bounds__(256) node_kernel(
    const float* __restrict__ edge_attr, const int* __restrict__ ei,
    const float* __restrict__ W_edge, const float* __restrict__ b_msg,
    const float* __restrict__ b_edge, const float* __restrict__ user_s,
    const float* __restrict__ W1, const float* __restrict__ b1) {
    __shared__ float CT[64 * 64];
    __shared__ float XM[64 * 64];
    __shared__ float sea0[64], sea1[64];
    __shared__ float sWe0[64], sWe1[64], sbc[64];

    const int t = threadIdx.x;
    const int b = blockIdx.x;
    const int base = b * 64;

#pragma unroll
    for (int i = 0; i < 16; i++) CT[t + i * 256] = 0.f;
    if (t < 64) {
        sea0[t] = 0.f; sea1[t] = 0.f;
        sWe0[t] = W_edge[t]; sWe1[t] = W_edge[64 + t];
        sbc[t] = b_msg[t] + b_edge[t];
    }
    {
        const float4* xmg = (const float4*)&g_xm[base * 64];
        float4* xms = (float4*)XM;
#pragma unroll
        for (int i = 0; i < 4; i++) xms[t + i * 256] = xmg[t + i * 256];
    }
    if (t < 64) {
        float u = b1[t];
#pragma unroll
        for (int k = 0; k < 32; k++) u += user_s[b * 32 + k] * W1[k * 64 + t];
        u = fmaxf(u, 0.f);
        __nv_bfloat16 h = __float2bfloat16(u);
        g_st_hi[b * STATE_W + 4096 + t] = h;
        g_st_lo[b * STATE_W + 4096 + t] =
            __float2bfloat16(u - __bfloat162float(h));
    }
    __syncthreads();

#pragma unroll
    for (int i = 0; i < 2; i++) {
        const int e = t + i * 256;
        const int eg = b * E_PG + e;
        const int s = ei[eg] - base;
        const int d = ei[TOT_E + eg] - base;
        const float2 ea = *(const float2*)&edge_attr[2 * eg];
        atomicAdd(&CT[s * 64 + d], 1.0f);
        atomicAdd(&sea0[d], ea.x);
        atomicAdd(&sea1[d], ea.y);
    }
    __syncthreads();

    const int tx = t & 15, ty = t >> 4;
    const int ci = tx * 4, dt = ty * 4;
    float acc[4][4];
    float dega[4] = {0.f, 0.f, 0.f, 0.f};
#pragma unroll
    for (int j = 0; j < 4; j++) {
        float4 v = *(const float4*)&g_xs[(base + dt + j) * 64 + ci];
        acc[j][0] = v.x; acc[j][1] = v.y; acc[j][2] = v.z; acc[j][3] = v.w;
    }
#pragma unroll 8
    for (int s = 0; s < 64; s++) {
        const float4 cv = *(const float4*)&CT[s * 64 + dt];
        const float4 xv = *(const float4*)&XM[s * 64 + ci];
        const float cj[4] = {cv.x, cv.y, cv.z, cv.w};
#pragma unroll
        for (int j = 0; j < 4; j++) {
            acc[j][0] += cj[j] * xv.x;
            acc[j][1] += cj[j] * xv.y;
            acc[j][2] += cj[j] * xv.z;
            acc[j][3] += cj[j] * xv.w;
            dega[j]   += cj[j];
        }
    }

#pragma unroll
    for (int j = 0; j < 4; j++) {
        const int d = dt + j;
        const unsigned mw = g_mask[(unsigned)(base + d) * 2u + (unsigned)(ci >> 5)];
        const float e0 = sea0[d], e1 = sea1[d], dg = dega[j];
        __nv_bfloat16 hv[4], lv[4];
#pragma unroll
        for (int k = 0; k < 4; k++) {
            const int c = ci + k;
            float val = acc[j][k] + e0 * sWe0[c] + e1 * sWe1[c] + dg * sbc[c];
            val = fmaxf(val, 0.f);
            val = ((mw >> (c & 31)) & 1u) ? val * 2.0f : 0.f;
            __nv_bfloat16 h = __float2bfloat16(val);
            hv[k] = h;
            lv[k] = __float2bfloat16(val - __bfloat162float(h));
        }
        const int idx = b * STATE_W + d * 64 + ci;
        *(__nv_bfloat162*)&g_st_hi[idx]     = __nv_bfloat162(hv[0], hv[1]);
        *(__nv_bfloat162*)&g_st_hi[idx + 2] = __nv_bfloat162(hv[2], hv[3]);
        *(__nv_bfloat162*)&g_st_lo[idx]     = __nv_bfloat162(lv[0], lv[1]);
        *(__nv_bfloat162*)&g_st_lo[idx + 2] = __nv_bfloat162(lv[2], lv[3]);
    }
}

// ====== async double-buffered tensor-core GEMM (bf16 3-MMA, 64x64 CTA) =====
// C = act(A @ B + bias); A,B pre-split bf16 hi/lo.
// CTA tile 64x64, 128 threads (4 warps, 2x2), warp tile 32x32, k-tile 32,
// 2 cp.async stages. Grid = (M/64, N/64) -> 2 CTAs/SM co-resident.

#define LDSM_X4(r0, r1, r2, r3, addr)                                        \
    asm volatile("ldmatrix.sync.aligned.m8n8.x4.shared.b16 {%0,%1,%2,%3}, [%4];" \
                 : "=r"(r0), "=r"(r1), "=r"(r2), "=r"(r3) : "r"(addr))

#define LDSM_X4_T(r0, r1, r2, r3, addr)                                      \
    asm volatile("ldmatrix.sync.aligned.m8n8.x4.trans.shared.b16 {%0,%1,%2,%3}, [%4];" \
                 : "=r"(r0), "=r"(r1), "=r"(r2), "=r"(r3) : "r"(addr))

#define MMA_BF16(d, a, b0, b1)                                               \
    asm volatile("mma.sync.aligned.m16n8k16.row.col.f32.bf16.bf16.f32 "      \
                 "{%0,%1,%2,%3}, {%4,%5,%6,%7}, {%8,%9}, {%0,%1,%2,%3};"     \
                 : "+f"(d[0]), "+f"(d[1]), "+f"(d[2]), "+f"(d[3])            \
                 : "r"(a[0]), "r"(a[1]), "r"(a[2]), "r"(a[3]),               \
                   "r"(b0), "r"(b1))

#define CP16(dst, src)                                                       \
    asm volatile("cp.async.cg.shared.global [%0], [%1], 16;" ::              \
                 "r"(dst), "l"(src))
#define CP_COMMIT() asm volatile("cp.async.commit_group;")
#define CP_WAIT1()  asm volatile("cp.async.wait_group 1;")
#define CP_WAIT0()  asm volatile("cp.async.wait_group 0;")

#define A_STRIDE 40            // elems: 32 + 8 pad (80 B rows)
#define B_STRIDE 72            // elems: 64 + 8 pad (144 B rows)
#define OFF_ALO  5120          // 64 * 80
#define OFF_BHI  10240         // 2 * 5120
#define OFF_BLO  14848         // + 32 * 144
#define STAGE_B  19456         // stage bytes
#define SMEM_TOT (2 * STAGE_B) // 38912

__global__ void __launch_bounds__(128) gemm_mma_async(
    const __nv_bfloat16* __restrict__ Ahi, const __nv_bfloat16* __restrict__ Alo,
    const __nv_bfloat16* __restrict__ Bhi, const __nv_bfloat16* __restrict__ Blo,
    const float* __restrict__ bias,
    __nv_bfloat16* __restrict__ Chi, __nv_bfloat16* __restrict__ Clo,
    float* __restrict__ Cf,
    int K, int Ntot, int do_relu) {
    extern __shared__ __align__(16) char smem[];

    const int t = threadIdx.x;
    const int lane = t & 31;
    const int warp = t >> 5;          // 0..3
    const int wm = warp & 1;          // M offset wm*32
    const int wn = warp >> 1;         // N offset wn*32
    const int row0 = blockIdx.x * 64;
    const int c0 = blockIdx.y * 64;

    // staging: A 64 rows x 32 k -> row = t>>1, col (t&1)*16 (2 CP16/matrix)
    //          B 32 rows x 64 n -> row = t>>2, col (t&3)*16 (2 CP16/matrix)
    const int arow = t >> 1, acol = (t & 1) * 16;
    const int brow = t >> 2, bcol = (t & 3) * 16;

    const size_t a_base = (size_t)(row0 + arow) * K + acol;
    const size_t b_base = (size_t)brow * Ntot + c0 + bcol;
    const unsigned a_dst = arow * 80 + acol * 2;
    const unsigned b_dst = brow * 144 + bcol * 2;

    unsigned u0;
    { unsigned tmp = (unsigned)__cvta_generic_to_shared(smem); u0 = tmp; }

    unsigned aoff[2];
#pragma unroll
    for (int mi = 0; mi < 2; mi++)
        aoff[mi] = ((wm * 32 + mi * 16 + (lane & 15)) * A_STRIDE +
                    (lane >> 4) * 8) * 2;
    unsigned boff[2];
#pragma unroll
    for (int g = 0; g < 2; g++)
        boff[g] = ((((lane >> 3) & 1) * 8 + (lane & 7)) * B_STRIDE +
                   wn * 32 + g * 16 + (lane >> 4) * 8) * 2;

    float acc[2][4][4];
#pragma unroll
    for (int mi = 0; mi < 2; mi++)
#pragma unroll
        for (int nj = 0; nj < 4; nj++)
#pragma unroll
            for (int i = 0; i < 4; i++) acc[mi][nj][i] = 0.f;

    const int nk = K / 32;

    // prologue: stage 0 <- tile 0
    {
        const unsigned s = u0;
        CP16(s + a_dst,                Ahi + a_base);
        CP16(s + a_dst + 16,           Ahi + a_base + 8);
        CP16(s + OFF_ALO + a_dst,      Alo + a_base);
        CP16(s + OFF_ALO + a_dst + 16, Alo + a_base + 8);
        CP16(s + OFF_BHI + b_dst,      Bhi + b_base);
        CP16(s + OFF_BHI + b_dst + 16, Bhi + b_base + 8);
        CP16(s + OFF_BLO + b_dst,      Blo + b_base);
        CP16(s + OFF_BLO + b_dst + 16, Blo + b_base + 8);
        CP_COMMIT();
    }

    for (int kt = 0; kt < nk; kt++) {
        __syncthreads();
        if (kt + 1 < nk) {
            const unsigned s = u0 + ((kt + 1) & 1) * STAGE_B;
            const size_t aoe = a_base + (size_t)(kt + 1) * 32;
            const size_t boe = b_base + (size_t)(kt + 1) * 32 * Ntot;
            CP16(s + a_dst,                Ahi + aoe);
            CP16(s + a_dst + 16,           Ahi + aoe + 8);
            CP16(s + OFF_ALO + a_dst,      Alo + aoe);
            CP16(s + OFF_ALO + a_dst + 16, Alo + aoe + 8);
            CP16(s + OFF_BHI + b_dst,      Bhi + boe);
            CP16(s + OFF_BHI + b_dst + 16, Bhi + boe + 8);
            CP16(s + OFF_BLO + b_dst,      Blo + boe);
            CP16(s + OFF_BLO + b_dst + 16, Blo + boe + 8);
            CP_COMMIT();
            CP_WAIT1();
        } else {
            CP_WAIT0();
        }
        __syncthreads();

        const unsigned sb = u0 + (kt & 1) * STAGE_B;
#pragma unroll
        for (int ks = 0; ks < 2; ks++) {
            unsigned ah[2][4], al[2][4];
#pragma unroll
            for (int mi = 0; mi < 2; mi++) {
                LDSM_X4(ah[mi][0], ah[mi][1], ah[mi][2], ah[mi][3],
                        sb + aoff[mi] + ks * 32);
                LDSM_X4(al[mi][0], al[mi][1], al[mi][2], al[mi][3],
                        sb + OFF_ALO + aoff[mi] + ks * 32);
            }
            unsigned bh[2][4], bl[2][4];
#pragma unroll
            for (int g = 0; g < 2; g++) {
                LDSM_X4_T(bh[g][0], bh[g][1], bh[g][2], bh[g][3],
                          sb + OFF_BHI + boff[g] + ks * (16 * B_STRIDE * 2));
                LDSM_X4_T(bl[g][0], bl[g][1], bl[g][2], bl[g][3],
                          sb + OFF_BLO + boff[g] + ks * (16 * B_STRIDE * 2));
            }
#pragma unroll
            for (int mi = 0; mi < 2; mi++)
#pragma unroll
                for (int nj = 0; nj < 4; nj++) {
                    const int g = nj >> 1, o = (nj & 1) * 2;
                    MMA_BF16(acc[mi][nj], ah[mi], bh[g][o], bh[g][o + 1]);
                    MMA_BF16(acc[mi][nj], ah[mi], bl[g][o], bl[g][o + 1]);
                    MMA_BF16(acc[mi][nj], al[mi], bh[g][o], bh[g][o + 1]);
                }
        }
    }

    // ---- epilogue: bias + relu, then fp32 OR bf16 hi/lo stores
    const int erow = lane >> 2;
    const int ecol = (lane & 3) * 2;
#pragma unroll
    for (int nj = 0; nj < 4; nj++) {
        const int c = c0 + wn * 32 + nj * 8 + ecol;
        const float bz0 = bias[c], bz1 = bias[c + 1];
#pragma unroll
        for (int mi = 0; mi < 2; mi++) {
            const int r = row0 + wm * 32 + mi * 16 + erow;
            float v0 = acc[mi][nj][0] + bz0;
            float v1 = acc[mi][nj][1] + bz1;
            float v2 = acc[mi][nj][2] + bz0;
            float v3 = acc[mi][nj][3] + bz1;
            if (do_relu) {
                v0 = fmaxf(v0, 0.f); v1 = fmaxf(v1, 0.f);
                v2 = fmaxf(v2, 0.f); v3 = fmaxf(v3, 0.f);
            }
            if (Cf) {
                *(float2*)&Cf[(size_t)r * Ntot + c] = make_float2(v0, v1);
                *(float2*)&Cf[(size_t)(r + 8) * Ntot + c] = make_float2(v2, v3);
            } else {
                __nv_bfloat16 h0 = __float2bfloat16(v0);
                __nv_bfloat16 h1 = __float2bfloat16(v1);
                __nv_bfloat16 h2 = __float2bfloat16(v2);
                __nv_bfloat16 h3 = __float2bfloat16(v3);
                *(__nv_bfloat162*)&Chi[(size_t)r * Ntot + c] =
                    __nv_bfloat162(h0, h1);
                *(__nv_bfloat162*)&Chi[(size_t)(r + 8) * Ntot + c] =
                    __nv_bfloat162(h2, h3);
                *(__nv_bfloat162*)&Clo[(size_t)r * Ntot + c] = __nv_bfloat162(
                    __float2bfloat16(v0 - __bfloat162float(h0)),
                    __float2bfloat16(v1 - __bfloat162float(h1)));
                *(__nv_bfloat162*)&Clo[(size_t)(r + 8) * Ntot + c] =
                    __nv_bfloat162(
                        __float2bfloat16(v2 - __bfloat162float(h2)),
                        __float2bfloat16(v3 - __bfloat162float(h3)));
            }
        }
    }
}

// ---------------- softmax across the batch axis (column-wise) --------------
__global__ void __launch_bounds__(256) softmax_kernel(float* __restrict__ out) {
    const int c = blockIdx.x;
    const int t = threadIdx.x;
    const int lane = t & 31, wid = t >> 5;
    __shared__ float redm[8];
    __shared__ float reds[8];

    float v[8];
    float mx = -1e30f;
#pragma unroll
    for (int i = 0; i < 8; i++) {
        v[i] = g_logits[(i * 256 + t) * 64 + c];
        mx = fmaxf(mx, v[i]);
    }
#pragma unroll
    for (int o = 16; o; o >>= 1) mx = fmaxf(mx, __shfl_xor_sync(~0u, mx, o));
    if (lane == 0) redm[wid] = mx;
    __syncthreads();
    mx = redm[0];
#pragma unroll
    for (int w = 1; w < 8; w++) mx = fmaxf(mx, redm[w]);

    float sum = 0.f;
#pragma unroll
    for (int i = 0; i < 8; i++) { v[i] = expf(v[i] - mx); sum += v[i]; }
#pragma unroll
    for (int o = 16; o; o >>= 1) sum += __shfl_xor_sync(~0u, sum, o);
    if (lane == 0) reds[wid] = sum;
    __syncthreads();
    sum = 0.f;
#pragma unroll
    for (int w = 0; w < 8; w++) sum += reds[w];
    const float inv = 1.0f / sum;

#pragma unroll
    for (int i = 0; i < 8; i++) out[(i * 256 + t) * 64 + c] = v[i] * inv;
}

// ---------------------------------------------------------------------------
extern "C" void kernel_launch(void* const* d_in, const int* in_sizes, int n_in,
                              void* d_out, int out_size) {
    const float* x         = (const float*)d_in[0];
    const float* edge_attr = (const float*)d_in[1];
    const float* user_s    = (const float*)d_in[2];
    const float* W_msg     = (const float*)d_in[3];
    const float* b_msg     = (const float*)d_in[4];
    const float* W_edge    = (const float*)d_in[5];
    const float* b_edge    = (const float*)d_in[6];
    const float* W_self    = (const float*)d_in[7];
    const float* b_self    = (const float*)d_in[8];
    const float* W1        = (const float*)d_in[9];
    const float* b1        = (const float*)d_in[10];
    const float* W2        = (const float*)d_in[11];
    const float* b2        = (const float*)d_in[12];
    const float* W3        = (const float*)d_in[13];
    const float* b3        = (const float*)d_in[14];
    const float* W4        = (const float*)d_in[15];
    const float* b4        = (const float*)d_in[16];
    const int*   ei        = (const int*)d_in[17];
    float* out = (float*)d_out;

    // idempotent, host-side, capture-safe — no static guard (harness rule)
    cudaFuncSetAttribute(gemm_mma_async,
                         cudaFuncAttributeMaxDynamicSharedMemorySize,
                         SMEM_TOT);

    __nv_bfloat16 *sthi, *stlo, *h1hi, *h1lo, *h2hi, *h2lo;
    __nv_bfloat16 *w2hi, *w2lo, *w3hi, *w3lo, *w4hi, *w4lo;
    float* logits;
    cudaGetSymbolAddress((void**)&sthi, g_st_hi);
    cudaGetSymbolAddress((void**)&stlo, g_st_lo);
    cudaGetSymbolAddress((void**)&h1hi, g_h1_hi);
    cudaGetSymbolAddress((void**)&h1lo, g_h1_lo);
    cudaGetSymbolAddress((void**)&h2hi, g_h2_hi);
    cudaGetSymbolAddress((void**)&h2lo, g_h2_lo);
    cudaGetSymbolAddress((void**)&w2hi, g_w2_hi);
    cudaGetSymbolAddress((void**)&w2lo, g_w2_lo);
    cudaGetSymbolAddress((void**)&w3hi, g_w3_hi);
    cudaGetSymbolAddress((void**)&w3lo, g_w3_lo);
    cudaGetSymbolAddress((void**)&w4hi, g_w4_hi);
    cudaGetSymbolAddress((void**)&w4lo, g_w4_lo);
    cudaGetSymbolAddress((void**)&logits, g_logits);

    mask_kernel<<<MASK_N / 256, 256>>>();
    xw_kernel<<<TOT_N / 64, 256>>>(x, W_msg, W_self, b_self);
    split_kernel<<<(STATE_W * HID + 255) / 256, 256>>>(W2, w2hi, w2lo,
                                                       STATE_W * HID);
    split_kernel<<<(HID * (HID / 2) + 255) / 256, 256>>>(W3, w3hi, w3lo,
                                                         HID * (HID / 2));
    split_kernel<<<((HID / 2) * N_NODE + 255) / 256, 256>>>(W4, w4hi, w4lo,
                                                            (HID / 2) * N_NODE);
    node_kernel<<<B_GR, 256>>>(edge_attr, ei, W_edge, b_msg, b_edge,
                               user_s, W1, b1);
    gemm_mma_async<<<dim3(B_GR / 64, HID / 64), 128, SMEM_TOT>>>(
        sthi, stlo, w2hi, w2lo, b2, h1hi, h1lo, nullptr, STATE_W, HID, 1);
    gemm_mma_async<<<dim3(B_GR / 64, (HID / 2) / 64), 128, SMEM_TOT>>>(
        h1hi, h1lo, w3hi, w3lo, b3, h2hi, h2lo, nullptr, HID, HID / 2, 1);
    gemm_mma_async<<<dim3(B_GR / 64, N_NODE / 64), 128, SMEM_TOT>>>(
        h2hi, h2lo, w4hi, w4lo, b4, nullptr, nullptr, logits, HID / 2,
        N_NODE, 0);
    softmax_kernel<<<N_NODE, 256>>>(out);
}